// round 13
// baseline (speedup 1.0000x reference)
#include <cuda_runtime.h>
#include <cuda_bf16.h>
#include <cstdint>

// Problem dims (fixed)
#define NN   8192
#define D0   128
#define D1   256
#define D2   256
#define QH   128
#define EPSV 1e-5f

// bigmm tiling: BM=64, BN=128, BK=32, 4 stages (swizzled), 2 CTAs/SM
#define BM       64
#define BNT      128
#define BKK      32
#define NIT      (NN / BKK)              // 256
#define SA_SZ    4096                    // 64 rows * 64B  (one A matrix)
#define SB_SZ    8192                    // 128 rows * 64B (one B matrix)
#define STAGE_SZ (2 * SA_SZ + 2 * SB_SZ) // 24576
#define NSTAGE   4
#define DSMEM_MM (NSTAGE * STAGE_SZ)     // 98304 -> 2 CTAs/SM

// ---------------- scratch ---------------------------------------------------
__device__ float g_x[NN * QH];           // Q-hidden
__device__ float g_h[NN * D2];           // hidden (h1 then h2)
__device__ float g_part[64 * 2 * D0];
__device__ float g_scale[D0];
__device__ float g_shift[D0];
__device__ __nv_bfloat16 g_Ahi[(size_t)NN * NN];   // A split hi
__device__ __nv_bfloat16 g_Alo[(size_t)NN * NN];   // A split lo
__device__ __nv_bfloat16 g_Bhi[(size_t)D1 * NN];   // Y^T hi [256, 8192]
__device__ __nv_bfloat16 g_Blo[(size_t)D1 * NN];   // Y^T lo

// ---------------- PTX helpers (baseline ISA) --------------------------------
__device__ __forceinline__ uint32_t smem_u32(const void* p) {
    uint32_t a;
    asm("{ .reg .u64 t; cvta.to.shared.u64 t, %1; cvt.u32.u64 %0, t; }" : "=r"(a) : "l"(p));
    return a;
}
__device__ __forceinline__ void cp_async16(uint32_t dst, const void* src) {
    asm volatile("cp.async.cg.shared.global [%0], [%1], 16;" :: "r"(dst), "l"(src) : "memory");
}
__device__ __forceinline__ void ldsm4(uint32_t& r0, uint32_t& r1, uint32_t& r2, uint32_t& r3,
                                      uint32_t a) {
    asm volatile("ldmatrix.sync.aligned.m8n8.x4.shared.b16 {%0,%1,%2,%3}, [%4];"
                 : "=r"(r0), "=r"(r1), "=r"(r2), "=r"(r3) : "r"(a));
}
__device__ __forceinline__ void mma_bf16(float* c, const uint32_t* a, const uint32_t* b) {
    asm volatile("mma.sync.aligned.m16n8k16.row.col.f32.bf16.bf16.f32 "
                 "{%0,%1,%2,%3}, {%4,%5,%6,%7}, {%8,%9}, {%0,%1,%2,%3};"
                 : "+f"(c[0]), "+f"(c[1]), "+f"(c[2]), "+f"(c[3])
                 : "r"(a[0]), "r"(a[1]), "r"(a[2]), "r"(a[3]), "r"(b[0]), "r"(b[1]));
}
__device__ __forceinline__ uint32_t pack_bf16x2(__nv_bfloat16 a, __nv_bfloat16 b) {
    uint16_t ua = *(uint16_t*)&a, ub = *(uint16_t*)&b;
    return (uint32_t)ua | ((uint32_t)ub << 16);
}
// swizzled 16B-chunk offset within a tile of 64B rows
__device__ __forceinline__ uint32_t swz(uint32_t row, uint32_t chunk) {
    return row * 64u + ((chunk ^ ((row >> 1) & 3u)) << 4);
}

// ---------------- batchnorm stats -> scale/shift -----------------------------
__global__ void bn_partial_kernel(const float* __restrict__ state) {
    int c = threadIdx.x, b = blockIdx.x;
    int r0 = b * (NN / 64);
    float s = 0.f, s2 = 0.f;
    #pragma unroll 4
    for (int r = 0; r < NN / 64; ++r) {
        float v = state[(size_t)(r0 + r) * D0 + c];
        s += v; s2 += v * v;
    }
    g_part[b * 2 * D0 + c]      = s;
    g_part[b * 2 * D0 + D0 + c] = s2;
}
__global__ void bn_final_kernel(const float* __restrict__ gamma,
                                const float* __restrict__ beta) {
    int c = threadIdx.x;
    float s = 0.f, s2 = 0.f;
    #pragma unroll
    for (int b = 0; b < 64; ++b) {
        s  += g_part[b * 2 * D0 + c];
        s2 += g_part[b * 2 * D0 + D0 + c];
    }
    float mean = s * (1.0f / NN);
    float var  = s2 * (1.0f / NN) - mean * mean;
    float sc = rsqrtf(var + EPSV) * gamma[c];
    g_scale[c] = sc;
    g_shift[c] = beta[c] - mean * sc;
}

// ---------------- A -> bf16 hi/lo split (one-time) ---------------------------
__global__ void __launch_bounds__(256)
convA_kernel(const float* __restrict__ A) {
    size_t i = ((size_t)blockIdx.x * blockDim.x + threadIdx.x) * 4;
    float4 v = *(const float4*)(A + i);
    float f[4] = {v.x, v.y, v.z, v.w};
    union { __nv_bfloat16 h[4]; unsigned long long u; } uh, ul;
    #pragma unroll
    for (int k = 0; k < 4; ++k) {
        uh.h[k] = __float2bfloat16(f[k]);
        ul.h[k] = __float2bfloat16(f[k] - __bfloat162float(uh.h[k]));
    }
    *(unsigned long long*)(g_Ahi + i) = uh.u;
    *(unsigned long long*)(g_Alo + i) = ul.u;
}

// ---------------- small SGEMM, optionally: fused BN on A, split-T output ----
template<bool BIAS, bool RELU, bool DOBN, bool TOUT>
__global__ void __launch_bounds__(256)
sgemm_kernel(const float* __restrict__ A, const float* __restrict__ B,
             const float* __restrict__ bias, float* __restrict__ C,
             __nv_bfloat16* __restrict__ outHi, __nv_bfloat16* __restrict__ outLo,
             int M, int N, int K) {
    constexpr int TBM = 64, TBN = 64, TBK = 16, TM = 4, TN = 4;
    __shared__ float As[TBK][TBM];
    __shared__ float Bs[TBK][TBN];
    __shared__ uint32_t ts[TOUT ? 64 * 65 : 1];
    const int tid = threadIdx.x;
    const int tx = tid % (TBN / TN);
    const int ty = tid / (TBN / TN);
    const int rowBase = blockIdx.y * TBM;
    const int colBase = blockIdx.x * TBN;
    const int aRow = tid / (TBK / 4);
    const int aCol = (tid % (TBK / 4)) * 4;
    const int bRow = tid / (TBN / 4);
    const int bCol = (tid % (TBN / 4)) * 4;
    float acc[TM][TN] = {};
    for (int k0 = 0; k0 < K; k0 += TBK) {
        float4 av = *(const float4*)(A + (size_t)(rowBase + aRow) * K + k0 + aCol);
        if (DOBN) {
            float4 sc = *(const float4*)(g_scale + k0 + aCol);
            float4 sh = *(const float4*)(g_shift + k0 + aCol);
            av.x = fmaf(av.x, sc.x, sh.x);
            av.y = fmaf(av.y, sc.y, sh.y);
            av.z = fmaf(av.z, sc.z, sh.z);
            av.w = fmaf(av.w, sc.w, sh.w);
        }
        As[aCol + 0][aRow] = av.x; As[aCol + 1][aRow] = av.y;
        As[aCol + 2][aRow] = av.z; As[aCol + 3][aRow] = av.w;
        float4 bv = *(const float4*)(B + (size_t)(k0 + bRow) * N + colBase + bCol);
        *(float4*)&Bs[bRow][bCol] = bv;
        __syncthreads();
        #pragma unroll
        for (int k = 0; k < TBK; ++k) {
            float4 a4 = *(const float4*)&As[k][ty * TM];
            float4 b4 = *(const float4*)&Bs[k][tx * TN];
            float a[TM] = {a4.x, a4.y, a4.z, a4.w};
            float b[TN] = {b4.x, b4.y, b4.z, b4.w};
            #pragma unroll
            for (int i = 0; i < TM; ++i)
                #pragma unroll
                for (int j = 0; j < TN; ++j)
                    acc[i][j] = fmaf(a[i], b[j], acc[i][j]);
        }
        __syncthreads();
    }

    if (!TOUT) {
        #pragma unroll
        for (int i = 0; i < TM; ++i) {
            int r = rowBase + ty * TM + i;
            #pragma unroll
            for (int j = 0; j < TN; ++j) {
                int c = colBase + tx * TN + j;
                float v = acc[i][j];
                if (BIAS) v += bias[c];
                if (RELU) v = fmaxf(v, 0.f);
                C[(size_t)r * N + c] = v;
            }
        }
    } else {
        #pragma unroll
        for (int i = 0; i < TM; ++i)
            #pragma unroll
            for (int j = 0; j < TN; ++j) {
                int cl = tx * TN + j, rl = ty * TM + i;
                float v = acc[i][j];
                __nv_bfloat16 hi = __float2bfloat16(v);
                __nv_bfloat16 lo = __float2bfloat16(v - __bfloat162float(hi));
                ts[cl * 65 + rl] = pack_bf16x2(hi, lo);
            }
        __syncthreads();
        #pragma unroll
        for (int i = 0; i < 8; ++i) {
            int id = i * 256 + tid;
            int cl = id >> 5, rp = (id & 31) * 2;
            uint32_t v0 = ts[cl * 65 + rp], v1 = ts[cl * 65 + rp + 1];
            uint32_t hh = (v0 & 0xFFFFu) | (v1 << 16);
            uint32_t ll = (v0 >> 16) | (v1 & 0xFFFF0000u);
            size_t o = (size_t)(colBase + cl) * NN + rowBase + rp;
            *(uint32_t*)(outHi + o) = hh;
            *(uint32_t*)(outLo + o) = ll;
        }
    }
}

// ---------------- big GEMM: C = relu(A @ B^T + bias) -------------------------
// A hi/lo [NN,NN] bf16 row-major (pre-split).  B hi/lo [256,NN] bf16 K-major.
// Tile 64x128xK32, 8 warps (warp tile 32x32), 4-stage swizzled pure-cp.async
// pipeline, 2 CTAs/SM.
__global__ void __launch_bounds__(256, 2)
bigmm_kernel(const __nv_bfloat16* __restrict__ Ahi, const __nv_bfloat16* __restrict__ Alo,
             const __nv_bfloat16* __restrict__ Bhi, const __nv_bfloat16* __restrict__ Blo,
             const float* __restrict__ bias, float* __restrict__ C) {
    extern __shared__ char sm[];
    const uint32_t sbase = smem_u32(sm);
    const int tid = threadIdx.x;
    const int n0 = blockIdx.x * BNT;
    const int m0 = blockIdx.y * BM;
    const int lrow = tid >> 2, lchk = tid & 3;

    // ---- loaders (pure cp.async: 6 per thread per stage) ----
    const __nv_bfloat16* gAh = Ahi + (size_t)(m0 + lrow) * NN + lchk * 8;
    const __nv_bfloat16* gAl = Alo + (size_t)(m0 + lrow) * NN + lchk * 8;
    const __nv_bfloat16* gBh = Bhi + (size_t)(n0 + lrow) * NN + lchk * 8;
    const __nv_bfloat16* gBl = Blo + (size_t)(n0 + lrow) * NN + lchk * 8;
    const uint32_t swA  = swz(lrow, lchk);
    const uint32_t swB0 = swz(lrow, lchk);
    const uint32_t swB1 = swz(lrow + 64, lchk);

    auto CP_ALL = [&](int s, int j) {
        uint32_t sb = sbase + s * STAGE_SZ;
        uint32_t sbB = sb + 2 * SA_SZ;
        size_t k = (size_t)j * BKK;
        cp_async16(sb + swA,          gAh + k);
        cp_async16(sb + SA_SZ + swA,  gAl + k);
        cp_async16(sbB + swB0,         gBh + k);
        cp_async16(sbB + swB0 + SB_SZ, gBl + k);
        cp_async16(sbB + swB1,         gBh + k + (size_t)64 * NN);
        cp_async16(sbB + swB1 + SB_SZ, gBl + k + (size_t)64 * NN);
        asm volatile("cp.async.commit_group;" ::: "memory");
    };

    // ---- compute mapping: 8 warps = 2(m) x 4(n), warp tile 32x32 ----
    const int wid = tid >> 5, lane = tid & 31;
    const int wm = wid & 1, wn = wid >> 1;
    const uint32_t rowA0 = wm * 32 + (lane & 15);
    const uint32_t ca    = lane >> 4;               // 0/1
    const uint32_t rowB0 = wn * 32 + ((lane >> 4) << 3) + (lane & 7);
    const uint32_t cb    = (lane >> 3) & 1;

    float acc[2][4][4];
    #pragma unroll
    for (int mt = 0; mt < 2; ++mt)
        #pragma unroll
        for (int nt = 0; nt < 4; ++nt)
            #pragma unroll
            for (int e = 0; e < 4; ++e) acc[mt][nt][e] = 0.f;

    // ---- prologue ----
    CP_ALL(0, 0);
    CP_ALL(1, 1);
    CP_ALL(2, 2);

    for (int j = 0; j < NIT; ++j) {
        const int rem = NIT - 1 - j;
        if (rem >= 2)      { asm volatile("cp.async.wait_group 2;" ::: "memory"); }
        else if (rem == 1) { asm volatile("cp.async.wait_group 1;" ::: "memory"); }
        else               { asm volatile("cp.async.wait_group 0;" ::: "memory"); }
        __syncthreads();
        if (j + 3 < NIT) CP_ALL((j + 3) & (NSTAGE - 1), j + 3);

        const uint32_t sb  = sbase + (j & (NSTAGE - 1)) * STAGE_SZ;
        const uint32_t sbB = sb + 2 * SA_SZ;
        #pragma unroll
        for (int kh = 0; kh < 2; ++kh) {
            uint32_t ah[2][4], al[2][4], bh[4][2], bl[4][2];
            #pragma unroll
            for (int mt = 0; mt < 2; ++mt) {
                uint32_t ad = sb + swz(rowA0 + mt * 16, kh * 2 + ca);
                ldsm4(ah[mt][0], ah[mt][1], ah[mt][2], ah[mt][3], ad);
                ldsm4(al[mt][0], al[mt][1], al[mt][2], al[mt][3], ad + SA_SZ);
            }
            #pragma unroll
            for (int p = 0; p < 2; ++p) {
                uint32_t bd = sbB + swz(rowB0 + p * 16, kh * 2 + cb);
                uint32_t r0, r1, r2, r3;
                ldsm4(r0, r1, r2, r3, bd);
                bh[2 * p][0] = r0; bh[2 * p][1] = r1;
                bh[2 * p + 1][0] = r2; bh[2 * p + 1][1] = r3;
                ldsm4(r0, r1, r2, r3, bd + SB_SZ);
                bl[2 * p][0] = r0; bl[2 * p][1] = r1;
                bl[2 * p + 1][0] = r2; bl[2 * p + 1][1] = r3;
            }
            #pragma unroll
            for (int mt = 0; mt < 2; ++mt)
                #pragma unroll
                for (int nt = 0; nt < 4; ++nt)
                    mma_bf16(acc[mt][nt], ah[mt], bh[nt]);
            #pragma unroll
            for (int mt = 0; mt < 2; ++mt)
                #pragma unroll
                for (int nt = 0; nt < 4; ++nt)
                    mma_bf16(acc[mt][nt], al[mt], bh[nt]);
            #pragma unroll
            for (int mt = 0; mt < 2; ++mt)
                #pragma unroll
                for (int nt = 0; nt < 4; ++nt)
                    mma_bf16(acc[mt][nt], ah[mt], bl[nt]);
        }
    }

    // ---- epilogue: bias + relu + store ----
    #pragma unroll
    for (int mt = 0; mt < 2; ++mt) {
        #pragma unroll
        for (int nt = 0; nt < 4; ++nt) {
            int r = m0 + wm * 32 + mt * 16 + (lane >> 2);
            int c = n0 + wn * 32 + nt * 8 + (lane & 3) * 2;
            float b0 = bias[c], b1 = bias[c + 1];
            float2 v0;
            v0.x = fmaxf(acc[mt][nt][0] + b0, 0.f);
            v0.y = fmaxf(acc[mt][nt][1] + b1, 0.f);
            *(float2*)(C + (size_t)r * 256 + c) = v0;
            float2 v1;
            v1.x = fmaxf(acc[mt][nt][2] + b0, 0.f);
            v1.y = fmaxf(acc[mt][nt][3] + b1, 0.f);
            *(float2*)(C + (size_t)(r + 8) * 256 + c) = v1;
        }
    }
}

// ---------------- final Q output --------------------------------------------
__global__ void qout_kernel(const float* __restrict__ T,
                            const float* __restrict__ Wq2,
                            const float* __restrict__ bq2,
                            float* __restrict__ out) {
    int warp = threadIdx.x >> 5;
    int lane = threadIdx.x & 31;
    int row  = blockIdx.x * 8 + warp;
    const float* t = T + (size_t)row * QH;
    float s = 0.f;
    #pragma unroll
    for (int k = lane; k < QH; k += 32) s += t[k] * Wq2[k];
    #pragma unroll
    for (int o = 16; o; o >>= 1) s += __shfl_xor_sync(0xffffffffu, s, o);
    if (lane == 0) out[row] = s + bq2[0];
}

// ---------------- launcher --------------------------------------------------
extern "C" void kernel_launch(void* const* d_in, const int* in_sizes, int n_in,
                              void* d_out, int out_size) {
    const float* state = (const float*)d_in[0];
    const float* adj   = (const float*)d_in[1];
    const float* gamma = (const float*)d_in[2];
    const float* beta  = (const float*)d_in[3];
    const float* W1    = (const float*)d_in[4];
    const float* b1    = (const float*)d_in[5];
    const float* W2    = (const float*)d_in[6];
    const float* b2    = (const float*)d_in[7];
    const float* Wq1   = (const float*)d_in[8];
    const float* bq1   = (const float*)d_in[9];
    const float* Wq2   = (const float*)d_in[10];
    const float* bq2   = (const float*)d_in[11];
    float* out = (float*)d_out;

    float *gx, *gh;
    cudaGetSymbolAddress((void**)&gx, g_x);
    cudaGetSymbolAddress((void**)&gh, g_h);
    __nv_bfloat16 *gAhi, *gAlo, *gBhi, *gBlo;
    cudaGetSymbolAddress((void**)&gAhi, g_Ahi);
    cudaGetSymbolAddress((void**)&gAlo, g_Alo);
    cudaGetSymbolAddress((void**)&gBhi, g_Bhi);
    cudaGetSymbolAddress((void**)&gBlo, g_Blo);

    cudaFuncSetAttribute(bigmm_kernel, cudaFuncAttributeMaxDynamicSharedMemorySize, DSMEM_MM);

    // A -> bf16 hi/lo (one-time, amortized over both big GEMMs)
    convA_kernel<<<(int)((size_t)NN * NN / 4 / 256), 256>>>(adj);

    // BatchNorm stats -> scale/shift
    bn_partial_kernel<<<64, D0>>>(state);
    bn_final_kernel<<<1, D0>>>(gamma, beta);

    // Y1^T(hi/lo) = split_T(bn(state) @ W1)
    sgemm_kernel<false, false, true, true>
        <<<dim3(D1 / 64, NN / 64), 256>>>(state, W1, nullptr, nullptr, gBhi, gBlo, NN, D1, D0);

    // h1 = relu(A @ Y1 + b1)
    bigmm_kernel<<<dim3(2, NN / BM), 256, DSMEM_MM>>>(gAhi, gAlo, gBhi, gBlo, b1, gh);

    // Y2^T(hi/lo) = split_T(h1 @ W2)
    sgemm_kernel<false, false, false, true>
        <<<dim3(D2 / 64, NN / 64), 256>>>(gh, W2, nullptr, nullptr, gBhi, gBlo, NN, D2, D1);

    // h2 = relu(A @ Y2 + b2)
    bigmm_kernel<<<dim3(2, NN / BM), 256, DSMEM_MM>>>(gAhi, gAlo, gBhi, gBlo, b2, gh);

    // Q head
    sgemm_kernel<true, true, false, false>
        <<<dim3(QH / 64, NN / 64), 256>>>(gh, Wq1, bq1, gx, nullptr, nullptr, NN, QH, D2);
    qout_kernel<<<NN / 8, 256>>>(gx, Wq2, bq2, out);
}

// round 14
// speedup vs baseline: 1.3817x; 1.3817x over previous
#include <cuda_runtime.h>
#include <cuda_bf16.h>
#include <cstdint>

// Problem dims (fixed)
#define NN   8192
#define D0   128
#define D1   256
#define D2   256
#define QH   128
#define EPSV 1e-5f

// bigmm tiling: CTA 128x128, BK=16, split-K=2, 8 warps (32x64), 4 stages
#define BM2      128
#define BN2      128
#define BK2      16
#define KSPL     2
#define KHALF    (NN / KSPL)             // 4096
#define NIT2     (KHALF / BK2)           // 256
#define PITCH2   48                      // 32B data + 16B pad per 16-elem bf16 row
#define AT_SZ    (128 * PITCH2)          // 6144 per matrix (A hi or lo; B hi or lo)
#define STAGE2   (4 * AT_SZ)             // 24576
#define NSTAGE2  4
#define DSMEM2   (NSTAGE2 * STAGE2)      // 98304 -> 2 CTAs/SM

// ---------------- scratch ---------------------------------------------------
__device__ float g_x[NN * QH];                      // Q-hidden
__device__ float g_h[NN * D2];                      // hidden (h1 then h2)
__device__ float g_pk[(size_t)KSPL * NN * 256];     // split-K partials
__device__ float g_part[64 * 2 * D0];
__device__ float g_scale[D0];
__device__ float g_shift[D0];
__device__ __nv_bfloat16 g_Bhi[(size_t)D1 * NN];    // Y^T hi [256, 8192]
__device__ __nv_bfloat16 g_Blo[(size_t)D1 * NN];    // Y^T lo

// ---------------- PTX helpers (baseline ISA) --------------------------------
__device__ __forceinline__ uint32_t smem_u32(const void* p) {
    uint32_t a;
    asm("{ .reg .u64 t; cvta.to.shared.u64 t, %1; cvt.u32.u64 %0, t; }" : "=r"(a) : "l"(p));
    return a;
}
__device__ __forceinline__ void cp_async16(uint32_t dst, const void* src) {
    asm volatile("cp.async.cg.shared.global [%0], [%1], 16;" :: "r"(dst), "l"(src) : "memory");
}
__device__ __forceinline__ void ldsm4(uint32_t& r0, uint32_t& r1, uint32_t& r2, uint32_t& r3,
                                      uint32_t a) {
    asm volatile("ldmatrix.sync.aligned.m8n8.x4.shared.b16 {%0,%1,%2,%3}, [%4];"
                 : "=r"(r0), "=r"(r1), "=r"(r2), "=r"(r3) : "r"(a));
}
__device__ __forceinline__ void mma_bf16(float* c, const uint32_t* a, const uint32_t* b) {
    asm volatile("mma.sync.aligned.m16n8k16.row.col.f32.bf16.bf16.f32 "
                 "{%0,%1,%2,%3}, {%4,%5,%6,%7}, {%8,%9}, {%0,%1,%2,%3};"
                 : "+f"(c[0]), "+f"(c[1]), "+f"(c[2]), "+f"(c[3])
                 : "r"(a[0]), "r"(a[1]), "r"(a[2]), "r"(a[3]), "r"(b[0]), "r"(b[1]));
}
__device__ __forceinline__ uint32_t pack_bf16x2(__nv_bfloat16 a, __nv_bfloat16 b) {
    uint16_t ua = *(uint16_t*)&a, ub = *(uint16_t*)&b;
    return (uint32_t)ua | ((uint32_t)ub << 16);
}

// ---------------- batchnorm stats -> scale/shift -----------------------------
__global__ void bn_partial_kernel(const float* __restrict__ state) {
    int c = threadIdx.x, b = blockIdx.x;
    int r0 = b * (NN / 64);
    float s = 0.f, s2 = 0.f;
    #pragma unroll 4
    for (int r = 0; r < NN / 64; ++r) {
        float v = state[(size_t)(r0 + r) * D0 + c];
        s += v; s2 += v * v;
    }
    g_part[b * 2 * D0 + c]      = s;
    g_part[b * 2 * D0 + D0 + c] = s2;
}
__global__ void bn_final_kernel(const float* __restrict__ gamma,
                                const float* __restrict__ beta) {
    int c = threadIdx.x;
    float s = 0.f, s2 = 0.f;
    #pragma unroll
    for (int b = 0; b < 64; ++b) {
        s  += g_part[b * 2 * D0 + c];
        s2 += g_part[b * 2 * D0 + D0 + c];
    }
    float mean = s * (1.0f / NN);
    float var  = s2 * (1.0f / NN) - mean * mean;
    float sc = rsqrtf(var + EPSV) * gamma[c];
    g_scale[c] = sc;
    g_shift[c] = beta[c] - mean * sc;
}

// ---------------- small SGEMM, optionally: fused BN on A, split-T output ----
template<bool BIAS, bool RELU, bool DOBN, bool TOUT>
__global__ void __launch_bounds__(256)
sgemm_kernel(const float* __restrict__ A, const float* __restrict__ B,
             const float* __restrict__ bias, float* __restrict__ C,
             __nv_bfloat16* __restrict__ outHi, __nv_bfloat16* __restrict__ outLo,
             int M, int N, int K) {
    constexpr int TBM = 64, TBN = 64, TBK = 16, TM = 4, TN = 4;
    __shared__ float As[TBK][TBM];
    __shared__ float Bs[TBK][TBN];
    __shared__ uint32_t ts[TOUT ? 64 * 65 : 1];
    const int tid = threadIdx.x;
    const int tx = tid % (TBN / TN);
    const int ty = tid / (TBN / TN);
    const int rowBase = blockIdx.y * TBM;
    const int colBase = blockIdx.x * TBN;
    const int aRow = tid / (TBK / 4);
    const int aCol = (tid % (TBK / 4)) * 4;
    const int bRow = tid / (TBN / 4);
    const int bCol = (tid % (TBN / 4)) * 4;
    float acc[TM][TN] = {};
    for (int k0 = 0; k0 < K; k0 += TBK) {
        float4 av = *(const float4*)(A + (size_t)(rowBase + aRow) * K + k0 + aCol);
        if (DOBN) {
            float4 sc = *(const float4*)(g_scale + k0 + aCol);
            float4 sh = *(const float4*)(g_shift + k0 + aCol);
            av.x = fmaf(av.x, sc.x, sh.x);
            av.y = fmaf(av.y, sc.y, sh.y);
            av.z = fmaf(av.z, sc.z, sh.z);
            av.w = fmaf(av.w, sc.w, sh.w);
        }
        As[aCol + 0][aRow] = av.x; As[aCol + 1][aRow] = av.y;
        As[aCol + 2][aRow] = av.z; As[aCol + 3][aRow] = av.w;
        float4 bv = *(const float4*)(B + (size_t)(k0 + bRow) * N + colBase + bCol);
        *(float4*)&Bs[bRow][bCol] = bv;
        __syncthreads();
        #pragma unroll
        for (int k = 0; k < TBK; ++k) {
            float4 a4 = *(const float4*)&As[k][ty * TM];
            float4 b4 = *(const float4*)&Bs[k][tx * TN];
            float a[TM] = {a4.x, a4.y, a4.z, a4.w};
            float b[TN] = {b4.x, b4.y, b4.z, b4.w};
            #pragma unroll
            for (int i = 0; i < TM; ++i)
                #pragma unroll
                for (int j = 0; j < TN; ++j)
                    acc[i][j] = fmaf(a[i], b[j], acc[i][j]);
        }
        __syncthreads();
    }

    if (!TOUT) {
        #pragma unroll
        for (int i = 0; i < TM; ++i) {
            int r = rowBase + ty * TM + i;
            #pragma unroll
            for (int j = 0; j < TN; ++j) {
                int c = colBase + tx * TN + j;
                float v = acc[i][j];
                if (BIAS) v += bias[c];
                if (RELU) v = fmaxf(v, 0.f);
                C[(size_t)r * N + c] = v;
            }
        }
    } else {
        #pragma unroll
        for (int i = 0; i < TM; ++i)
            #pragma unroll
            for (int j = 0; j < TN; ++j) {
                int cl = tx * TN + j, rl = ty * TM + i;
                float v = acc[i][j];
                __nv_bfloat16 hi = __float2bfloat16(v);
                __nv_bfloat16 lo = __float2bfloat16(v - __bfloat162float(hi));
                ts[cl * 65 + rl] = pack_bf16x2(hi, lo);
            }
        __syncthreads();
        #pragma unroll
        for (int i = 0; i < 8; ++i) {
            int id = i * 256 + tid;
            int cl = id >> 5, rp = (id & 31) * 2;
            uint32_t v0 = ts[cl * 65 + rp], v1 = ts[cl * 65 + rp + 1];
            uint32_t hh = (v0 & 0xFFFFu) | (v1 << 16);
            uint32_t ll = (v0 >> 16) | (v1 & 0xFFFF0000u);
            size_t o = (size_t)(colBase + cl) * NN + rowBase + rp;
            *(uint32_t*)(outHi + o) = hh;
            *(uint32_t*)(outLo + o) = ll;
        }
    }
}

// ---------------- big GEMM (split-K): P = A_half @ B_half^T ------------------
// A fp32 [NN,NN] row-major (hi/lo split in-kernel).  B hi/lo [256,NN] K-major.
// CTA tile 128x128, BK=16, 8 warps (warp tile 32x64), 4-stage pipeline,
// pitch-48 conflict-free smem, 2 CTAs/SM.  Writes fp32 partial (no bias/relu).
__global__ void __launch_bounds__(256, 2)
bigmm_kernel(const float* __restrict__ A,
             const __nv_bfloat16* __restrict__ Bhi, const __nv_bfloat16* __restrict__ Blo,
             float* __restrict__ P) {
    extern __shared__ char sm[];
    const uint32_t sbase = smem_u32(sm);
    const int tid = threadIdx.x;
    const int n0 = blockIdx.x * BN2;
    const int m0 = blockIdx.y * BM2;
    const int kz = blockIdx.z * KHALF;
    float* __restrict__ Pz = P + (size_t)blockIdx.z * NN * 256;

    // ---- loaders: 2 threads per row (128 rows), 32B fp32 A / 16B bf16 B ----
    const int lrow = tid & 127, lhalf = tid >> 7;
    const float* gA = A + (size_t)(m0 + lrow) * NN + kz + lhalf * 8;
    const __nv_bfloat16* gBh = Bhi + (size_t)(n0 + lrow) * NN + kz + lhalf * 8;
    const __nv_bfloat16* gBl = Blo + (size_t)(n0 + lrow) * NN + kz + lhalf * 8;
    const uint32_t rowoff = (uint32_t)lrow * PITCH2 + lhalf * 16;

    float4 rA[2];
    auto LDG_A = [&](int j) {
        const float* p = gA + (size_t)j * BK2;
        rA[0] = *(const float4*)(p + 0);
        rA[1] = *(const float4*)(p + 4);
    };
    auto STS_A = [&](int s) {
        const float* f = (const float*)rA;
        uint32_t hbuf[4], lbuf[4];
        #pragma unroll
        for (int e = 0; e < 4; ++e) {
            float x0 = f[2 * e], x1 = f[2 * e + 1];
            __nv_bfloat16 h0 = __float2bfloat16(x0);
            __nv_bfloat16 h1 = __float2bfloat16(x1);
            __nv_bfloat16 l0 = __float2bfloat16(x0 - __bfloat162float(h0));
            __nv_bfloat16 l1 = __float2bfloat16(x1 - __bfloat162float(h1));
            hbuf[e] = pack_bf16x2(h0, h1);
            lbuf[e] = pack_bf16x2(l0, l1);
        }
        char* d = sm + s * STAGE2 + rowoff;
        *(uint4*)(d)         = *(uint4*)hbuf;
        *(uint4*)(d + AT_SZ) = *(uint4*)lbuf;
    };
    auto CP_B = [&](int s, int j) {
        uint32_t d = sbase + s * STAGE2 + 2 * AT_SZ + rowoff;
        size_t k = (size_t)j * BK2;
        cp_async16(d,         gBh + k);
        cp_async16(d + AT_SZ, gBl + k);
        asm volatile("cp.async.commit_group;" ::: "memory");
    };

    // ---- compute mapping: 8 warps = 4(m) x 2(n), warp tile 32x64 ----
    const int wid = tid >> 5, lane = tid & 31;
    const int wm = wid & 3, wn = wid >> 2;
    const uint32_t rowA0 = wm * 32 + (lane & 15);
    const uint32_t ca    = lane >> 4;               // 0/1
    const uint32_t rowB0 = wn * 64 + ((lane >> 4) << 3) + (lane & 7);
    const uint32_t cb    = (lane >> 3) & 1;

    float acc[2][8][4];
    #pragma unroll
    for (int mt = 0; mt < 2; ++mt)
        #pragma unroll
        for (int nt = 0; nt < 8; ++nt)
            #pragma unroll
            for (int e = 0; e < 4; ++e) acc[mt][nt][e] = 0.f;

    // ---- prologue ----
    LDG_A(0); STS_A(0); CP_B(0, 0);
    LDG_A(1); STS_A(1); CP_B(1, 1);
    LDG_A(2); STS_A(2); CP_B(2, 2);
    LDG_A(3);

    for (int j = 0; j < NIT2; ++j) {
        const int rem = NIT2 - 1 - j;
        if (rem >= 2)      { asm volatile("cp.async.wait_group 2;" ::: "memory"); }
        else if (rem == 1) { asm volatile("cp.async.wait_group 1;" ::: "memory"); }
        else               { asm volatile("cp.async.wait_group 0;" ::: "memory"); }
        __syncthreads();
        if (j + 3 < NIT2) {
            const int ls = (j + 3) & (NSTAGE2 - 1);
            STS_A(ls);                 // rA holds data for iteration j+3
            CP_B(ls, j + 3);
        }
        if (j + 4 < NIT2) LDG_A(j + 4);

        const uint32_t sb  = sbase + (j & (NSTAGE2 - 1)) * STAGE2;
        const uint32_t sbB = sb + 2 * AT_SZ;

        uint32_t ah[2][4], al[2][4], bb[8][2];
        #pragma unroll
        for (int mt = 0; mt < 2; ++mt) {
            uint32_t ad = sb + (rowA0 + mt * 16) * PITCH2 + ca * 16;
            ldsm4(ah[mt][0], ah[mt][1], ah[mt][2], ah[mt][3], ad);
            ldsm4(al[mt][0], al[mt][1], al[mt][2], al[mt][3], ad + AT_SZ);
        }
        // B hi fragments
        #pragma unroll
        for (int p = 0; p < 4; ++p) {
            uint32_t bd = sbB + (rowB0 + p * 16) * PITCH2 + cb * 16;
            uint32_t r0, r1, r2, r3;
            ldsm4(r0, r1, r2, r3, bd);
            bb[2 * p][0] = r0; bb[2 * p][1] = r1;
            bb[2 * p + 1][0] = r2; bb[2 * p + 1][1] = r3;
        }
        #pragma unroll
        for (int mt = 0; mt < 2; ++mt)
            #pragma unroll
            for (int nt = 0; nt < 8; ++nt)
                mma_bf16(acc[mt][nt], ah[mt], bb[nt]);
        #pragma unroll
        for (int mt = 0; mt < 2; ++mt)
            #pragma unroll
            for (int nt = 0; nt < 8; ++nt)
                mma_bf16(acc[mt][nt], al[mt], bb[nt]);
        // B lo fragments reuse bb registers
        #pragma unroll
        for (int p = 0; p < 4; ++p) {
            uint32_t bd = sbB + AT_SZ + (rowB0 + p * 16) * PITCH2 + cb * 16;
            uint32_t r0, r1, r2, r3;
            ldsm4(r0, r1, r2, r3, bd);
            bb[2 * p][0] = r0; bb[2 * p][1] = r1;
            bb[2 * p + 1][0] = r2; bb[2 * p + 1][1] = r3;
        }
        #pragma unroll
        for (int mt = 0; mt < 2; ++mt)
            #pragma unroll
            for (int nt = 0; nt < 8; ++nt)
                mma_bf16(acc[mt][nt], ah[mt], bb[nt]);
    }

    // ---- epilogue: store fp32 partial ----
    #pragma unroll
    for (int mt = 0; mt < 2; ++mt) {
        #pragma unroll
        for (int nt = 0; nt < 8; ++nt) {
            int r = m0 + wm * 32 + mt * 16 + (lane >> 2);
            int c = n0 + wn * 64 + nt * 8 + (lane & 3) * 2;
            float2 v0 = {acc[mt][nt][0], acc[mt][nt][1]};
            float2 v1 = {acc[mt][nt][2], acc[mt][nt][3]};
            *(float2*)(Pz + (size_t)r * 256 + c) = v0;
            *(float2*)(Pz + (size_t)(r + 8) * 256 + c) = v1;
        }
    }
}

// ---------------- split-K reduce: C = relu(P0 + P1 + bias) -------------------
__global__ void __launch_bounds__(256)
kreduce_kernel(const float* __restrict__ bias, float* __restrict__ C) {
    size_t i = ((size_t)blockIdx.x * 256 + threadIdx.x) * 4;
    int c = (int)(i & 255);
    float4 a = *(const float4*)(g_pk + i);
    float4 b = *(const float4*)(g_pk + (size_t)NN * 256 + i);
    float4 bi = *(const float4*)(bias + c);
    float4 o;
    o.x = fmaxf(a.x + b.x + bi.x, 0.f);
    o.y = fmaxf(a.y + b.y + bi.y, 0.f);
    o.z = fmaxf(a.z + b.z + bi.z, 0.f);
    o.w = fmaxf(a.w + b.w + bi.w, 0.f);
    *(float4*)(C + i) = o;
}

// ---------------- final Q output --------------------------------------------
__global__ void qout_kernel(const float* __restrict__ T,
                            const float* __restrict__ Wq2,
                            const float* __restrict__ bq2,
                            float* __restrict__ out) {
    int warp = threadIdx.x >> 5;
    int lane = threadIdx.x & 31;
    int row  = blockIdx.x * 8 + warp;
    const float* t = T + (size_t)row * QH;
    float s = 0.f;
    #pragma unroll
    for (int k = lane; k < QH; k += 32) s += t[k] * Wq2[k];
    #pragma unroll
    for (int o = 16; o; o >>= 1) s += __shfl_xor_sync(0xffffffffu, s, o);
    if (lane == 0) out[row] = s + bq2[0];
}

// ---------------- launcher --------------------------------------------------
extern "C" void kernel_launch(void* const* d_in, const int* in_sizes, int n_in,
                              void* d_out, int out_size) {
    const float* state = (const float*)d_in[0];
    const float* adj   = (const float*)d_in[1];
    const float* gamma = (const float*)d_in[2];
    const float* beta  = (const float*)d_in[3];
    const float* W1    = (const float*)d_in[4];
    const float* b1    = (const float*)d_in[5];
    const float* W2    = (const float*)d_in[6];
    const float* b2    = (const float*)d_in[7];
    const float* Wq1   = (const float*)d_in[8];
    const float* bq1   = (const float*)d_in[9];
    const float* Wq2   = (const float*)d_in[10];
    const float* bq2   = (const float*)d_in[11];
    float* out = (float*)d_out;

    float *gx, *gh, *gpk;
    cudaGetSymbolAddress((void**)&gx, g_x);
    cudaGetSymbolAddress((void**)&gh, g_h);
    cudaGetSymbolAddress((void**)&gpk, g_pk);
    __nv_bfloat16 *gBhi, *gBlo;
    cudaGetSymbolAddress((void**)&gBhi, g_Bhi);
    cudaGetSymbolAddress((void**)&gBlo, g_Blo);

    cudaFuncSetAttribute(bigmm_kernel, cudaFuncAttributeMaxDynamicSharedMemorySize, DSMEM2);

    // BatchNorm stats -> scale/shift
    bn_partial_kernel<<<64, D0>>>(state);
    bn_final_kernel<<<1, D0>>>(gamma, beta);

    // Y1^T(hi/lo) = split_T(bn(state) @ W1)
    sgemm_kernel<false, false, true, true>
        <<<dim3(D1 / 64, NN / 64), 256>>>(state, W1, nullptr, nullptr, gBhi, gBlo, NN, D1, D0);

    // h1 = relu(A @ Y1 + b1)   — split-K partials + reduce
    bigmm_kernel<<<dim3(2, NN / BM2, KSPL), 256, DSMEM2>>>(adj, gBhi, gBlo, gpk);
    kreduce_kernel<<<(NN * 256) / (256 * 4), 256>>>(b1, gh);

    // Y2^T(hi/lo) = split_T(h1 @ W2)
    sgemm_kernel<false, false, false, true>
        <<<dim3(D2 / 64, NN / 64), 256>>>(gh, W2, nullptr, nullptr, gBhi, gBlo, NN, D2, D1);

    // h2 = relu(A @ Y2 + b2)
    bigmm_kernel<<<dim3(2, NN / BM2, KSPL), 256, DSMEM2>>>(adj, gBhi, gBlo, gpk);
    kreduce_kernel<<<(NN * 256) / (256 * 4), 256>>>(b2, gh);

    // Q head
    sgemm_kernel<true, true, false, false>
        <<<dim3(QH / 64, NN / 64), 256>>>(gh, Wq1, bq1, gx, nullptr, nullptr, NN, QH, D2);
    qout_kernel<<<NN / 8, 256>>>(gx, Wq2, bq2, out);
}